// round 4
// baseline (speedup 1.0000x reference)
#include <cuda_runtime.h>

#define T_CTX 4096
#define E_DIM 768
#define H_DIM 64
#define B_SZ  8
#define M_ROWS (B_SZ * T_CTX)   // 32768

typedef unsigned long long ull;

__device__ float g_q[M_ROWS * H_DIM];
__device__ float g_k[M_ROWS * H_DIM];
__device__ float g_v[M_ROWS * H_DIM];

// ---- packed f32x2 helpers (FFMA2 path; ptxas never emits from plain C++) ----
__device__ __forceinline__ ull pk2(float lo, float hi) {
    ull r; asm("mov.b64 %0, {%1,%2};" : "=l"(r) : "f"(lo), "f"(hi)); return r;
}
__device__ __forceinline__ void upk2(ull v, float& lo, float& hi) {
    asm("mov.b64 {%0,%1}, %2;" : "=f"(lo), "=f"(hi) : "l"(v));
}
__device__ __forceinline__ ull fma2(ull a, ull b, ull c) {
    ull d; asm("fma.rn.f32x2 %0, %1, %2, %3;" : "=l"(d) : "l"(a), "l"(b), "l"(c));
    return d;
}
__device__ __forceinline__ ull mul2(ull a, ull b) {
    ull d; asm("mul.rn.f32x2 %0, %1, %2;" : "=l"(d) : "l"(a), "l"(b));
    return d;
}

// ---------------------------------------------------------------------------
// Fused projection: reads x once, produces q, k, v.
// Tile 64 rows x 192 cols (Wq|Wk|Wv). 256 threads, thread tile 4x12.
// ---------------------------------------------------------------------------
__global__ __launch_bounds__(256) void proj_fused(const float* __restrict__ x,
                                                  const float* __restrict__ Wq,
                                                  const float* __restrict__ Wk,
                                                  const float* __restrict__ Wv) {
    __shared__ float xs[64][33];
    __shared__ float ws[32][192];

    const int tid = threadIdx.x;
    const int tx = tid & 15;
    const int ty = tid >> 4;
    const int m0 = blockIdx.x * 64;

    ull acc2[4][6];
#pragma unroll
    for (int i = 0; i < 4; i++)
#pragma unroll
        for (int p = 0; p < 6; p++) acc2[i][p] = 0ULL;

    for (int k0 = 0; k0 < E_DIM; k0 += 32) {
        __syncthreads();
#pragma unroll
        for (int i = 0; i < 8; i++) {            // 64x32 x-tile
            int idx = i * 256 + tid;
            int r = idx >> 5, c = idx & 31;
            xs[r][c] = x[(size_t)(m0 + r) * E_DIM + k0 + c];
        }
        const float* Ws[3] = {Wq, Wk, Wv};
#pragma unroll
        for (int w = 0; w < 3; w++) {
#pragma unroll
            for (int i = 0; i < 8; i++) {        // 32x64 W-tile per head
                int idx = i * 256 + tid;
                int r = idx >> 6, c = idx & 63;
                ws[r][w * 64 + c] = Ws[w][(size_t)(k0 + r) * H_DIM + c];
            }
        }
        __syncthreads();

#pragma unroll 8
        for (int kk = 0; kk < 32; kk++) {
            ull a2[4];
#pragma unroll
            for (int i = 0; i < 4; i++) {
                float a = xs[ty * 4 + i][kk];
                a2[i] = pk2(a, a);
            }
            ull b2[6];
#pragma unroll
            for (int w = 0; w < 3; w++) {
                const float4 b4 =
                    *reinterpret_cast<const float4*>(&ws[kk][w * 64 + tx * 4]);
                b2[w * 2]     = pk2(b4.x, b4.y);
                b2[w * 2 + 1] = pk2(b4.z, b4.w);
            }
#pragma unroll
            for (int i = 0; i < 4; i++)
#pragma unroll
                for (int p = 0; p < 6; p++)
                    acc2[i][p] = fma2(a2[i], b2[p], acc2[i][p]);
        }
    }

    float* outs[3] = {g_q, g_k, g_v};
#pragma unroll
    for (int w = 0; w < 3; w++)
#pragma unroll
        for (int i = 0; i < 4; i++) {
            float o0, o1, o2, o3;
            upk2(acc2[i][w * 2], o0, o1);
            upk2(acc2[i][w * 2 + 1], o2, o3);
            *reinterpret_cast<float4*>(
                &outs[w][(size_t)(m0 + ty * 4 + i) * H_DIM + tx * 4]) =
                make_float4(o0, o1, o2, o3);
        }
}

// ---------------------------------------------------------------------------
// Causal flash attention. Q-tile 128, K-tile 64. 256 threads, thread tile 8x4.
// Q and P stored transposed so the 8-row operand is a broadcast LDS.128 pair.
// qt order reversed: heavy CTAs launch first (work ~ 2qt+2).
// ---------------------------------------------------------------------------
#define PQ 132
#define PK 68
#define PP 132
#define ATT_SMEM_FLOATS (64 * PQ + 64 * PK + 64 * 64 + 64 * PP)
#define ATT_SMEM_BYTES  (ATT_SMEM_FLOATS * 4)

__global__ __launch_bounds__(256, 2) void attn2(float* __restrict__ out) {
    extern __shared__ float sm[];
    float* Qst = sm;                  // [h][qrow]   pitch PQ (h-major)
    float* Kst = Qst + 64 * PQ;       // [h][key]    pitch PK
    float* Vs  = Kst + 64 * PK;       // [key][h]    pitch 64
    float* Pst = Vs + 64 * 64;        // [key][qrow] pitch PP

    const int tid = threadIdx.x;
    const int tx = tid & 15;          // 4 h / key columns
    const int ty = tid >> 4;          // 8 q rows: ty*8 .. ty*8+7
    const int b  = blockIdx.y;
    const int qt = (gridDim.x - 1) - blockIdx.x;   // heavy first
    const int q0 = qt * 128;

    const float* qb = g_q + ((size_t)b * T_CTX + q0) * H_DIM;
#pragma unroll
    for (int i = 0; i < 32; i++) {    // 128x64 transpose into Qst
        int idx = i * 256 + tid;
        int r = idx >> 6, h = idx & 63;
        Qst[h * PQ + r] = qb[idx];
    }

    ull O2[4][4];
    float m_i[8], l_i[8];
#pragma unroll
    for (int i = 0; i < 4; i++)
#pragma unroll
        for (int j = 0; j < 4; j++) O2[i][j] = 0ULL;
#pragma unroll
    for (int r = 0; r < 8; r++) { m_i[r] = -1e30f; l_i[r] = 0.f; }

    const int nk = 2 * qt + 2;
    for (int kt = 0; kt < nk; kt++) {
        __syncthreads();
        const float* kb = g_k + ((size_t)b * T_CTX + (size_t)kt * 64) * H_DIM;
        const float* vb = g_v + ((size_t)b * T_CTX + (size_t)kt * 64) * H_DIM;
#pragma unroll
        for (int i = 0; i < 16; i++) {
            int idx = i * 256 + tid;
            int r = idx >> 6, h = idx & 63;
            Kst[h * PK + r] = kb[idx];
            Vs[idx]         = vb[idx];
        }
        __syncthreads();

        // ---- S = Q K^T : 16 FFMA2 + 4 packs + 3 LDS.128 per kk ----
        ull S2[4][4];
#pragma unroll
        for (int i = 0; i < 4; i++)
#pragma unroll
            for (int j = 0; j < 4; j++) S2[i][j] = 0ULL;

#pragma unroll 8
        for (int kk = 0; kk < 64; kk++) {
            const float4 alo = *reinterpret_cast<const float4*>(&Qst[kk * PQ + ty * 8]);
            const float4 ahi = *reinterpret_cast<const float4*>(&Qst[kk * PQ + ty * 8 + 4]);
            const float4 bv  = *reinterpret_cast<const float4*>(&Kst[kk * PK + tx * 4]);
            ull a2[4] = {pk2(alo.x, alo.y), pk2(alo.z, alo.w),
                         pk2(ahi.x, ahi.y), pk2(ahi.z, ahi.w)};
            ull b2[4] = {pk2(bv.x, bv.x), pk2(bv.y, bv.y),
                         pk2(bv.z, bv.z), pk2(bv.w, bv.w)};
#pragma unroll
            for (int i = 0; i < 4; i++)
#pragma unroll
                for (int j = 0; j < 4; j++)
                    S2[i][j] = fma2(a2[i], b2[j], S2[i][j]);
        }

        float s[8][4];
#pragma unroll
        for (int i = 0; i < 4; i++)
#pragma unroll
            for (int j = 0; j < 4; j++)
                upk2(S2[i][j], s[2 * i][j], s[2 * i + 1][j]);

        // causal mask (only the last two K-tiles touch the diagonal)
        if (kt >= 2 * qt) {
            const int kb0 = kt * 64;
#pragma unroll
            for (int r = 0; r < 8; r++) {
                const int qrow = q0 + ty * 8 + r;
#pragma unroll
                for (int j = 0; j < 4; j++)
                    if (kb0 + tx * 4 + j > qrow) s[r][j] = -1e30f;
            }
        }

        // ---- online softmax (16-lane groups) ----
        float alpha[8];
#pragma unroll
        for (int r = 0; r < 8; r++) {
            float rm = fmaxf(fmaxf(s[r][0], s[r][1]), fmaxf(s[r][2], s[r][3]));
#pragma unroll
            for (int off = 8; off >= 1; off >>= 1)
                rm = fmaxf(rm, __shfl_xor_sync(0xffffffffu, rm, off, 16));
            float mnew = fmaxf(m_i[r], rm);
            alpha[r] = __expf(m_i[r] - mnew);
            m_i[r] = mnew;
            float rsum = 0.f;
#pragma unroll
            for (int j = 0; j < 4; j++) {
                float p = __expf(s[r][j] - mnew);
                s[r][j] = p;
                rsum += p;
            }
#pragma unroll
            for (int off = 8; off >= 1; off >>= 1)
                rsum += __shfl_xor_sync(0xffffffffu, rsum, off, 16);
            l_i[r] = l_i[r] * alpha[r] + rsum;
        }
#pragma unroll
        for (int i = 0; i < 4; i++) {
            const ull al2 = pk2(alpha[2 * i], alpha[2 * i + 1]);
#pragma unroll
            for (int j = 0; j < 4; j++) O2[i][j] = mul2(O2[i][j], al2);
        }

        // ---- publish P transposed: Pst[key][qrow] ----
#pragma unroll
        for (int j = 0; j < 4; j++) {
            *reinterpret_cast<float4*>(&Pst[(tx * 4 + j) * PP + ty * 8]) =
                make_float4(s[0][j], s[1][j], s[2][j], s[3][j]);
            *reinterpret_cast<float4*>(&Pst[(tx * 4 + j) * PP + ty * 8 + 4]) =
                make_float4(s[4][j], s[5][j], s[6][j], s[7][j]);
        }
        __syncthreads();

        // ---- O += P V : 16 FFMA2 + 4 packs + 3 LDS.128 per kk ----
#pragma unroll 8
        for (int kk = 0; kk < 64; kk++) {
            const float4 plo = *reinterpret_cast<const float4*>(&Pst[kk * PP + ty * 8]);
            const float4 phi = *reinterpret_cast<const float4*>(&Pst[kk * PP + ty * 8 + 4]);
            const float4 vv  = *reinterpret_cast<const float4*>(&Vs[kk * 64 + tx * 4]);
            ull p2[4] = {pk2(plo.x, plo.y), pk2(plo.z, plo.w),
                         pk2(phi.x, phi.y), pk2(phi.z, phi.w)};
            ull v2[4] = {pk2(vv.x, vv.x), pk2(vv.y, vv.y),
                         pk2(vv.z, vv.z), pk2(vv.w, vv.w)};
#pragma unroll
            for (int i = 0; i < 4; i++)
#pragma unroll
                for (int j = 0; j < 4; j++)
                    O2[i][j] = fma2(p2[i], v2[j], O2[i][j]);
        }
    }

    // ---- epilogue ----
    float* ob = out + ((size_t)b * T_CTX + q0) * H_DIM;
#pragma unroll
    for (int i = 0; i < 4; i++) {
        float o[2][4];
#pragma unroll
        for (int j = 0; j < 4; j++) upk2(O2[i][j], o[0][j], o[1][j]);
#pragma unroll
        for (int u = 0; u < 2; u++) {
            const int r = 2 * i + u;
            const float inv = 1.f / l_i[r];
            *reinterpret_cast<float4*>(&ob[(ty * 8 + r) * H_DIM + tx * 4]) =
                make_float4(o[u][0] * inv, o[u][1] * inv,
                            o[u][2] * inv, o[u][3] * inv);
        }
    }
}

// ---------------------------------------------------------------------------
extern "C" void kernel_launch(void* const* d_in, const int* in_sizes, int n_in,
                              void* d_out, int out_size) {
    const float* x  = (const float*)d_in[0];
    const float* Wq = (const float*)d_in[1];
    const float* Wk = (const float*)d_in[2];
    const float* Wv = (const float*)d_in[3];
    float* out = (float*)d_out;

    cudaFuncSetAttribute(attn2,
                         cudaFuncAttributeMaxDynamicSharedMemorySize,
                         ATT_SMEM_BYTES);

    proj_fused<<<M_ROWS / 64, 256>>>(x, Wq, Wk, Wv);
    attn2<<<dim3(T_CTX / 128, B_SZ), 256, ATT_SMEM_BYTES>>>(out);
}

// round 5
// speedup vs baseline: 1.0025x; 1.0025x over previous
#include <cuda_runtime.h>

#define T_CTX 4096
#define E_DIM 768
#define H_DIM 64
#define B_SZ  8
#define M_ROWS (B_SZ * T_CTX)   // 32768

typedef unsigned long long ull;

__device__ float g_q[M_ROWS * H_DIM];
__device__ float g_k[M_ROWS * H_DIM];
__device__ float g_v[M_ROWS * H_DIM];

// ---- packed f32x2 helpers (FFMA2 path; ptxas never emits from plain C++) ----
__device__ __forceinline__ ull pk2(float lo, float hi) {
    ull r; asm("mov.b64 %0, {%1,%2};" : "=l"(r) : "f"(lo), "f"(hi)); return r;
}
__device__ __forceinline__ void upk2(ull v, float& lo, float& hi) {
    asm("mov.b64 {%0,%1}, %2;" : "=f"(lo), "=f"(hi) : "l"(v));
}
__device__ __forceinline__ ull fma2(ull a, ull b, ull c) {
    ull d; asm("fma.rn.f32x2 %0, %1, %2, %3;" : "=l"(d) : "l"(a), "l"(b), "l"(c));
    return d;
}
__device__ __forceinline__ ull mul2(ull a, ull b) {
    ull d; asm("mul.rn.f32x2 %0, %1, %2;" : "=l"(d) : "l"(a), "l"(b));
    return d;
}

// ---------------------------------------------------------------------------
// Fused projection: reads x once, produces q, k, v.
// Tile 64 rows x 192 cols (Wq|Wk|Wv). 256 threads, thread tile 4x12.
// ---------------------------------------------------------------------------
__global__ __launch_bounds__(256) void proj_fused(const float* __restrict__ x,
                                                  const float* __restrict__ Wq,
                                                  const float* __restrict__ Wk,
                                                  const float* __restrict__ Wv) {
    __shared__ float xs[64][33];
    __shared__ float ws[32][192];

    const int tid = threadIdx.x;
    const int tx = tid & 15;
    const int ty = tid >> 4;
    const int m0 = blockIdx.x * 64;

    ull acc2[4][6];
#pragma unroll
    for (int i = 0; i < 4; i++)
#pragma unroll
        for (int p = 0; p < 6; p++) acc2[i][p] = 0ULL;

    for (int k0 = 0; k0 < E_DIM; k0 += 32) {
        __syncthreads();
#pragma unroll
        for (int i = 0; i < 8; i++) {            // 64x32 x-tile
            int idx = i * 256 + tid;
            int r = idx >> 5, c = idx & 31;
            xs[r][c] = x[(size_t)(m0 + r) * E_DIM + k0 + c];
        }
        const float* Ws[3] = {Wq, Wk, Wv};
#pragma unroll
        for (int w = 0; w < 3; w++) {
#pragma unroll
            for (int i = 0; i < 8; i++) {        // 32x64 W-tile per head
                int idx = i * 256 + tid;
                int r = idx >> 6, c = idx & 63;
                ws[r][w * 64 + c] = Ws[w][(size_t)(k0 + r) * H_DIM + c];
            }
        }
        __syncthreads();

#pragma unroll 8
        for (int kk = 0; kk < 32; kk++) {
            ull a2[4];
#pragma unroll
            for (int i = 0; i < 4; i++) {
                float a = xs[ty * 4 + i][kk];
                a2[i] = pk2(a, a);
            }
            ull b2[6];
#pragma unroll
            for (int w = 0; w < 3; w++) {
                const float4 b4 =
                    *reinterpret_cast<const float4*>(&ws[kk][w * 64 + tx * 4]);
                b2[w * 2]     = pk2(b4.x, b4.y);
                b2[w * 2 + 1] = pk2(b4.z, b4.w);
            }
#pragma unroll
            for (int i = 0; i < 4; i++)
#pragma unroll
                for (int p = 0; p < 6; p++)
                    acc2[i][p] = fma2(a2[i], b2[p], acc2[i][p]);
        }
    }

    float* outs[3] = {g_q, g_k, g_v};
#pragma unroll
    for (int w = 0; w < 3; w++)
#pragma unroll
        for (int i = 0; i < 4; i++) {
            float o0, o1, o2, o3;
            upk2(acc2[i][w * 2], o0, o1);
            upk2(acc2[i][w * 2 + 1], o2, o3);
            *reinterpret_cast<float4*>(
                &outs[w][(size_t)(m0 + ty * 4 + i) * H_DIM + tx * 4]) =
                make_float4(o0, o1, o2, o3);
        }
}

// ---------------------------------------------------------------------------
// Causal flash attention. Q-tile 128, K-tile 64. 256 threads, thread tile 8x4.
// Q and P stored transposed so the 8-row operand is a broadcast LDS.128 pair.
// qt order reversed: heavy CTAs launch first (work ~ 2qt+2).
// ---------------------------------------------------------------------------
#define PQ 132
#define PK 68
#define PP 132
#define ATT_SMEM_FLOATS (64 * PQ + 64 * PK + 64 * 64 + 64 * PP)
#define ATT_SMEM_BYTES  (ATT_SMEM_FLOATS * 4)

__global__ __launch_bounds__(256, 2) void attn2(float* __restrict__ out) {
    extern __shared__ float sm[];
    float* Qst = sm;                  // [h][qrow]   pitch PQ (h-major)
    float* Kst = Qst + 64 * PQ;       // [h][key]    pitch PK
    float* Vs  = Kst + 64 * PK;       // [key][h]    pitch 64
    float* Pst = Vs + 64 * 64;        // [key][qrow] pitch PP

    const int tid = threadIdx.x;
    const int tx = tid & 15;          // 4 h / key columns
    const int ty = tid >> 4;          // 8 q rows: ty*8 .. ty*8+7
    const int b  = blockIdx.y;
    const int qt = (gridDim.x - 1) - blockIdx.x;   // heavy first
    const int q0 = qt * 128;

    const float* qb = g_q + ((size_t)b * T_CTX + q0) * H_DIM;
#pragma unroll
    for (int i = 0; i < 32; i++) {    // 128x64 transpose into Qst
        int idx = i * 256 + tid;
        int r = idx >> 6, h = idx & 63;
        Qst[h * PQ + r] = qb[idx];
    }

    ull O2[4][4];
    float m_i[8], l_i[8];
#pragma unroll
    for (int i = 0; i < 4; i++)
#pragma unroll
        for (int j = 0; j < 4; j++) O2[i][j] = 0ULL;
#pragma unroll
    for (int r = 0; r < 8; r++) { m_i[r] = -1e30f; l_i[r] = 0.f; }

    const int nk = 2 * qt + 2;
    for (int kt = 0; kt < nk; kt++) {
        __syncthreads();
        const float* kb = g_k + ((size_t)b * T_CTX + (size_t)kt * 64) * H_DIM;
        const float* vb = g_v + ((size_t)b * T_CTX + (size_t)kt * 64) * H_DIM;
#pragma unroll
        for (int i = 0; i < 16; i++) {
            int idx = i * 256 + tid;
            int r = idx >> 6, h = idx & 63;
            Kst[h * PK + r] = kb[idx];
            Vs[idx]         = vb[idx];
        }
        __syncthreads();

        // ---- S = Q K^T : 16 FFMA2 + 4 packs + 3 LDS.128 per kk ----
        ull S2[4][4];
#pragma unroll
        for (int i = 0; i < 4; i++)
#pragma unroll
            for (int j = 0; j < 4; j++) S2[i][j] = 0ULL;

#pragma unroll 8
        for (int kk = 0; kk < 64; kk++) {
            const float4 alo = *reinterpret_cast<const float4*>(&Qst[kk * PQ + ty * 8]);
            const float4 ahi = *reinterpret_cast<const float4*>(&Qst[kk * PQ + ty * 8 + 4]);
            const float4 bv  = *reinterpret_cast<const float4*>(&Kst[kk * PK + tx * 4]);
            ull a2[4] = {pk2(alo.x, alo.y), pk2(alo.z, alo.w),
                         pk2(ahi.x, ahi.y), pk2(ahi.z, ahi.w)};
            ull b2[4] = {pk2(bv.x, bv.x), pk2(bv.y, bv.y),
                         pk2(bv.z, bv.z), pk2(bv.w, bv.w)};
#pragma unroll
            for (int i = 0; i < 4; i++)
#pragma unroll
                for (int j = 0; j < 4; j++)
                    S2[i][j] = fma2(a2[i], b2[j], S2[i][j]);
        }

        float s[8][4];
#pragma unroll
        for (int i = 0; i < 4; i++)
#pragma unroll
            for (int j = 0; j < 4; j++)
                upk2(S2[i][j], s[2 * i][j], s[2 * i + 1][j]);

        // causal mask (only the last two K-tiles touch the diagonal)
        if (kt >= 2 * qt) {
            const int kb0 = kt * 64;
#pragma unroll
            for (int r = 0; r < 8; r++) {
                const int qrow = q0 + ty * 8 + r;
#pragma unroll
                for (int j = 0; j < 4; j++)
                    if (kb0 + tx * 4 + j > qrow) s[r][j] = -1e30f;
            }
        }

        // ---- online softmax (16-lane groups) ----
        float alpha[8];
#pragma unroll
        for (int r = 0; r < 8; r++) {
            float rm = fmaxf(fmaxf(s[r][0], s[r][1]), fmaxf(s[r][2], s[r][3]));
#pragma unroll
            for (int off = 8; off >= 1; off >>= 1)
                rm = fmaxf(rm, __shfl_xor_sync(0xffffffffu, rm, off, 16));
            float mnew = fmaxf(m_i[r], rm);
            alpha[r] = __expf(m_i[r] - mnew);
            m_i[r] = mnew;
            float rsum = 0.f;
#pragma unroll
            for (int j = 0; j < 4; j++) {
                float p = __expf(s[r][j] - mnew);
                s[r][j] = p;
                rsum += p;
            }
#pragma unroll
            for (int off = 8; off >= 1; off >>= 1)
                rsum += __shfl_xor_sync(0xffffffffu, rsum, off, 16);
            l_i[r] = l_i[r] * alpha[r] + rsum;
        }
#pragma unroll
        for (int i = 0; i < 4; i++) {
            const ull al2 = pk2(alpha[2 * i], alpha[2 * i + 1]);
#pragma unroll
            for (int j = 0; j < 4; j++) O2[i][j] = mul2(O2[i][j], al2);
        }

        // ---- publish P transposed: Pst[key][qrow] ----
#pragma unroll
        for (int j = 0; j < 4; j++) {
            *reinterpret_cast<float4*>(&Pst[(tx * 4 + j) * PP + ty * 8]) =
                make_float4(s[0][j], s[1][j], s[2][j], s[3][j]);
            *reinterpret_cast<float4*>(&Pst[(tx * 4 + j) * PP + ty * 8 + 4]) =
                make_float4(s[4][j], s[5][j], s[6][j], s[7][j]);
        }
        __syncthreads();

        // ---- O += P V : 16 FFMA2 + 4 packs + 3 LDS.128 per kk ----
#pragma unroll 8
        for (int kk = 0; kk < 64; kk++) {
            const float4 plo = *reinterpret_cast<const float4*>(&Pst[kk * PP + ty * 8]);
            const float4 phi = *reinterpret_cast<const float4*>(&Pst[kk * PP + ty * 8 + 4]);
            const float4 vv  = *reinterpret_cast<const float4*>(&Vs[kk * 64 + tx * 4]);
            ull p2[4] = {pk2(plo.x, plo.y), pk2(plo.z, plo.w),
                         pk2(phi.x, phi.y), pk2(phi.z, phi.w)};
            ull v2[4] = {pk2(vv.x, vv.x), pk2(vv.y, vv.y),
                         pk2(vv.z, vv.z), pk2(vv.w, vv.w)};
#pragma unroll
            for (int i = 0; i < 4; i++)
#pragma unroll
                for (int j = 0; j < 4; j++)
                    O2[i][j] = fma2(p2[i], v2[j], O2[i][j]);
        }
    }

    // ---- epilogue ----
    float* ob = out + ((size_t)b * T_CTX + q0) * H_DIM;
#pragma unroll
    for (int i = 0; i < 4; i++) {
        float o[2][4];
#pragma unroll
        for (int j = 0; j < 4; j++) upk2(O2[i][j], o[0][j], o[1][j]);
#pragma unroll
        for (int u = 0; u < 2; u++) {
            const int r = 2 * i + u;
            const float inv = 1.f / l_i[r];
            *reinterpret_cast<float4*>(&ob[(ty * 8 + r) * H_DIM + tx * 4]) =
                make_float4(o[u][0] * inv, o[u][1] * inv,
                            o[u][2] * inv, o[u][3] * inv);
        }
    }
}

// ---------------------------------------------------------------------------
extern "C" void kernel_launch(void* const* d_in, const int* in_sizes, int n_in,
                              void* d_out, int out_size) {
    const float* x  = (const float*)d_in[0];
    const float* Wq = (const float*)d_in[1];
    const float* Wk = (const float*)d_in[2];
    const float* Wv = (const float*)d_in[3];
    float* out = (float*)d_out;

    cudaFuncSetAttribute(attn2,
                         cudaFuncAttributeMaxDynamicSharedMemorySize,
                         ATT_SMEM_BYTES);

    proj_fused<<<M_ROWS / 64, 256>>>(x, Wq, Wk, Wv);
    attn2<<<dim3(T_CTX / 128, B_SZ), 256, ATT_SMEM_BYTES>>>(out);
}